// round 15
// baseline (speedup 1.0000x reference)
#include <cuda_runtime.h>
#include <cuda_bf16.h>
#include <math.h>
#include <stdint.h>

// Problem constants (fixed by the reference)
#define NHEAD 8
#define NLVL 4
#define NPNT 4
#define BB 4
#define NQ 8000
#define CC 256
#define DH 32
#define STOT 19947   // 100*150 + 50*75 + 25*38 + 13*19

// Scratch (static device globals: allocation-free)
static __device__ float g_value[(size_t)BB * STOT * CC];     // [B,S,C]
static __device__ float g_qc   [(size_t)BB * NQ * 384];      // fused [off(256) | logits(128)]
static __device__ float g_tout [(size_t)BB * NQ * CC];

// Pre-split packed weights: per fp32 -> 3 bf16 [hi, lo, hi]; row = 256*3 = 768 bf16
static __device__ __nv_bfloat16 g_wp_val[(size_t)256 * 768];
static __device__ __nv_bfloat16 g_wp_q  [(size_t)384 * 768];   // W_off rows 0..255, W_attn rows 256..383
static __device__ __nv_bfloat16 g_wp_out[(size_t)256 * 768];
static __device__ float g_bcat[384];

// ---------------------------------------------------------------------------
// Weight pre-split: W[row][j] -> Wp[row*768 + j*3 + {0,1,2}] = hi, lo, hi
// ---------------------------------------------------------------------------
__global__ void conv_w3(const float* __restrict__ W, __nv_bfloat16* __restrict__ out, int n)
{
    int i = blockIdx.x * 256 + threadIdx.x;
    if (i >= n) return;
    int row = i >> 8, j = i & 255;       // K = 256
    float x = W[i];
    __nv_bfloat16 h = __float2bfloat16(x);
    __nv_bfloat16 l = __float2bfloat16(x - __bfloat162float(h));
    __nv_bfloat16* p = out + (size_t)row * 768 + j * 3;
    p[0] = h; p[1] = l; p[2] = h;
}

__global__ void biascat(const float* __restrict__ b0, const float* __restrict__ b1,
                        float* __restrict__ out)
{
    int i = blockIdx.x * 256 + threadIdx.x;
    if (i < 256) out[i] = b0[i];
    else if (i < 384) out[i] = b1[i - 256];
}

// ---------------------------------------------------------------------------
// Split-bf16 tensor-core GEMM (HMMA mma.sync path; tcgen05 unavailable at
// the harness's compute_103 PTX target).
// C[m,n] = sum_k A[m,k]*W[n,k] + bias[n]; fp32 in/out.
// A converted in-loop to [hi,hi,lo]; W pre-packed [hi,lo,hi] (exact 3-product
// split: hiA*hiB + hiA*loB + loA*hiB, err ~2^-17).
// CTA tile 128x128, 8 warps (warp tile 64x32), k-tile = 16 fp32 = 48 bf16.
// ---------------------------------------------------------------------------
#define GSS 56           // padded smem row stride in bf16 (conflict-free)

__device__ __forceinline__ void mma16816(float* d, const uint32_t* a, const uint32_t* b)
{
    asm volatile(
        "mma.sync.aligned.m16n8k16.row.col.f32.bf16.bf16.f32 "
        "{%0,%1,%2,%3}, {%4,%5,%6,%7}, {%8,%9}, {%0,%1,%2,%3};\n"
        : "+f"(d[0]), "+f"(d[1]), "+f"(d[2]), "+f"(d[3])
        : "r"(a[0]), "r"(a[1]), "r"(a[2]), "r"(a[3]), "r"(b[0]), "r"(b[1]));
}

__device__ __forceinline__ void split_pack_A(float4 v, unsigned short* u)
{
    const float f[4] = {v.x, v.y, v.z, v.w};
#pragma unroll
    for (int j = 0; j < 4; j++) {
        __nv_bfloat16 h = __float2bfloat16(f[j]);
        __nv_bfloat16 l = __float2bfloat16(f[j] - __bfloat162float(h));
        unsigned short hb = __bfloat16_as_ushort(h);
        unsigned short lb = __bfloat16_as_ushort(l);
        u[3 * j + 0] = hb; u[3 * j + 1] = hb; u[3 * j + 2] = lb;
    }
}

__device__ __forceinline__ void store12(__nv_bfloat16* base, const unsigned short* u)
{
    uint2* dst = reinterpret_cast<uint2*>(base);
    uint2 w0, w1, w2;
    w0.x = (uint32_t)u[0]  | ((uint32_t)u[1]  << 16);
    w0.y = (uint32_t)u[2]  | ((uint32_t)u[3]  << 16);
    w1.x = (uint32_t)u[4]  | ((uint32_t)u[5]  << 16);
    w1.y = (uint32_t)u[6]  | ((uint32_t)u[7]  << 16);
    w2.x = (uint32_t)u[8]  | ((uint32_t)u[9]  << 16);
    w2.y = (uint32_t)u[10] | ((uint32_t)u[11] << 16);
    dst[0] = w0; dst[1] = w1; dst[2] = w2;
}

__global__ __launch_bounds__(256, 2) void gemm_ws(
    const float* __restrict__ A, const __nv_bfloat16* __restrict__ Wp,
    const float* __restrict__ bias, float* __restrict__ C,
    int M, int N, int K)
{
    __shared__ __nv_bfloat16 As[128 * GSS];
    __shared__ __nv_bfloat16 Bs[128 * GSS];

    const int tid  = threadIdx.x;
    const int lane = tid & 31;
    const int warp = tid >> 5;
    const int warpM = warp & 1;       // 0..1  (64-row groups)
    const int warpN = warp >> 1;      // 0..3  (32-col groups)
    const int m0 = blockIdx.x * 128;
    const int n0 = blockIdx.y * 128;

    float acc[4][4][4];
#pragma unroll
    for (int i = 0; i < 4; i++)
#pragma unroll
        for (int j = 0; j < 4; j++)
#pragma unroll
            for (int r = 0; r < 4; r++) acc[i][j][r] = 0.f;

    // A loader: 512 float4-chunks per tile, 2 per thread
    const int ar0 = tid >> 2,          ac0 = tid & 3;
    const int ar1 = (tid + 256) >> 2,  ac1 = (tid + 256) & 3;
    // W loader: per tile 128 rows x 6 uint4 (48 bf16 = 96B/row) = 768 chunks, 3 per thread
    int wr[3], wsg[3];
#pragma unroll
    for (int i = 0; i < 3; i++) {
        int c = tid + i * 256;
        wr[i] = c / 6; wsg[i] = c % 6;
    }
    const uint4* WpV = reinterpret_cast<const uint4*>(Wp);   // row stride = 96 uint4

    float4 pa0, pa1;
    uint4 pw[3];

    // prefetch tile 0
    {
        pa0 = make_float4(0.f, 0.f, 0.f, 0.f); pa1 = pa0;
        if (m0 + ar0 < M) pa0 = reinterpret_cast<const float4*>(A + (size_t)(m0 + ar0) * K)[ac0];
        if (m0 + ar1 < M) pa1 = reinterpret_cast<const float4*>(A + (size_t)(m0 + ar1) * K)[ac1];
#pragma unroll
        for (int i = 0; i < 3; i++)
            pw[i] = WpV[(size_t)(n0 + wr[i]) * 96 + wsg[i]];
    }

    const int nTiles = K / 16;
    for (int t = 0; t < nTiles; t++) {
        __syncthreads();
        {
            unsigned short u[12];
            split_pack_A(pa0, u); store12(&As[ar0 * GSS + ac0 * 12], u);
            split_pack_A(pa1, u); store12(&As[ar1 * GSS + ac1 * 12], u);
#pragma unroll
            for (int i = 0; i < 3; i++)
                *reinterpret_cast<uint4*>(&Bs[wr[i] * GSS + wsg[i] * 8]) = pw[i];
        }
        __syncthreads();

        if (t + 1 < nTiles) {
            const int k0 = (t + 1) * 16;
            pa0 = make_float4(0.f, 0.f, 0.f, 0.f); pa1 = pa0;
            if (m0 + ar0 < M) pa0 = reinterpret_cast<const float4*>(A + (size_t)(m0 + ar0) * K + k0)[ac0];
            if (m0 + ar1 < M) pa1 = reinterpret_cast<const float4*>(A + (size_t)(m0 + ar1) * K + k0)[ac1];
#pragma unroll
            for (int i = 0; i < 3; i++)
                pw[i] = WpV[(size_t)(n0 + wr[i]) * 96 + (t + 1) * 6 + wsg[i]];
        }

        // compute: 3 k16-steps over the 48 bf16 slots
#pragma unroll
        for (int ks = 0; ks < 3; ks++) {
            uint32_t bfr[4][2];
#pragma unroll
            for (int an = 0; an < 4; an++) {
                const uint32_t* bp = reinterpret_cast<const uint32_t*>(
                    &Bs[(warpN * 32 + an * 8 + (lane >> 2)) * GSS + ks * 16 + (lane & 3) * 2]);
                bfr[an][0] = bp[0];
                bfr[an][1] = bp[4];      // +8 bf16
            }
#pragma unroll
            for (int am = 0; am < 4; am++) {
                const uint32_t* ap = reinterpret_cast<const uint32_t*>(
                    &As[(warpM * 64 + am * 16 + (lane >> 2)) * GSS + ks * 16 + (lane & 3) * 2]);
                uint32_t afr[4];
                afr[0] = ap[0];
                afr[1] = ap[8 * GSS / 2];        // +8 rows
                afr[2] = ap[4];                  // +8 bf16
                afr[3] = ap[8 * GSS / 2 + 4];
#pragma unroll
                for (int an = 0; an < 4; an++)
                    mma16816(acc[am][an], afr, bfr[an]);
            }
        }
    }

    // epilogue: add bias, store fp32
#pragma unroll
    for (int an = 0; an < 4; an++) {
        const int col = n0 + warpN * 32 + an * 8 + (lane & 3) * 2;
        const float b0v = bias[col], b1v = bias[col + 1];
#pragma unroll
        for (int am = 0; am < 4; am++) {
            const int row = m0 + warpM * 64 + am * 16 + (lane >> 2);
            if (row < M) {
                float2* p = reinterpret_cast<float2*>(C + (size_t)row * N + col);
                *p = make_float2(acc[am][an][0] + b0v, acc[am][an][1] + b1v);
            }
            if (row + 8 < M) {
                float2* p = reinterpret_cast<float2*>(C + (size_t)(row + 8) * N + col);
                *p = make_float2(acc[am][an][2] + b0v, acc[am][an][3] + b1v);
            }
        }
    }
}

// ---------------------------------------------------------------------------
// Fused softmax + bilinear sampling + attention reduce.
// Reads the fused query GEMM output qc: [B*Nq, 384] = [off(256) | logits(128)].
// One warp per (b, q, h); g = lane>>3 point slot, c = lane&7 float4 group.
// ---------------------------------------------------------------------------
__global__ __launch_bounds__(256) void msda_sampler(
    const float* __restrict__ value, const float* __restrict__ qc,
    const float* __restrict__ refp, float* __restrict__ out)
{
    constexpr int LH[NLVL] = {100, 50, 25, 13};
    constexpr int LW[NLVL] = {150, 75, 38, 19};
    constexpr int LS[NLVL] = {0, 15000, 18750, 19700};

    const int gw   = (blockIdx.x << 3) + (threadIdx.x >> 5);
    const int lane = threadIdx.x & 31;
    if (gw >= BB * NQ * NHEAD) return;

    const int h  = gw & 7;
    const int bq = gw >> 3;
    const int b  = bq / NQ;
    const unsigned FULL = 0xffffffffu;

    const float* qrow = qc + (size_t)bq * 384;

    // softmax over the 16 logits (cols 256 + h*16 ...)
    const float* lg = qrow + 256 + h * 16;
    float myl = (lane < 16) ? lg[lane] : -1e30f;
    float mx = myl;
#pragma unroll
    for (int o = 16; o >= 1; o >>= 1) mx = fmaxf(mx, __shfl_xor_sync(FULL, mx, o));
    float e = (lane < 16) ? expf(myl - mx) : 0.f;
    float s = e;
#pragma unroll
    for (int o = 16; o >= 1; o >>= 1) s += __shfl_xor_sync(FULL, s, o);
    const float aw = e * (1.f / s);

    float px = 0.f, py = 0.f;
    if (lane < 16) {
        const int l = lane >> 2;
        const float2 o2 = *reinterpret_cast<const float2*>(qrow + h * 32 + lane * 2);
        const float2 r2 = *reinterpret_cast<const float2*>(refp + (size_t)bq * (NLVL * 2) + l * 2);
        const float fW = (l == 0) ? 150.f : (l == 1) ? 75.f : (l == 2) ? 38.f : 19.f;
        const float fH = (l == 0) ? 100.f : (l == 1) ? 50.f : (l == 2) ? 25.f : 13.f;
        px = (r2.x + o2.x / fW) * fW - 0.5f;
        py = (r2.y + o2.y / fH) * fH - 0.5f;
    }

    const int g  = lane >> 3;
    const int c4 = (lane & 7) << 2;
    float4 acc = make_float4(0.f, 0.f, 0.f, 0.f);

#pragma unroll
    for (int l = 0; l < NLVL; l++) {
        const int Hd = LH[l], Wd = LW[l];
        const int src = (l << 2) + g;
        const float xP  = __shfl_sync(FULL, px, src);
        const float yP  = __shfl_sync(FULL, py, src);
        const float awP = __shfl_sync(FULL, aw, src);

        const float xf = floorf(xP), yf = floorf(yP);
        const float wx1 = xP - xf, wy1 = yP - yf;
        const float wx0 = 1.f - wx1, wy0 = 1.f - wy1;
        const int ix0 = (int)xf, iy0 = (int)yf;
        const int ix1 = ix0 + 1, iy1 = iy0 + 1;

        const bool vx0 = (ix0 >= 0) & (ix0 < Wd);
        const bool vx1 = (ix1 >= 0) & (ix1 < Wd);
        const bool vy0 = (iy0 >= 0) & (iy0 < Hd);
        const bool vy1 = (iy1 >= 0) & (iy1 < Hd);

        const float* vb = value + ((size_t)(b * STOT + LS[l])) * CC + h * DH + c4;
        float4 v00 = make_float4(0.f, 0.f, 0.f, 0.f);
        float4 v10 = v00, v01 = v00, v11 = v00;
        if (vx0 & vy0) v00 = *reinterpret_cast<const float4*>(vb + (size_t)(iy0 * Wd + ix0) * CC);
        if (vx1 & vy0) v10 = *reinterpret_cast<const float4*>(vb + (size_t)(iy0 * Wd + ix1) * CC);
        if (vx0 & vy1) v01 = *reinterpret_cast<const float4*>(vb + (size_t)(iy1 * Wd + ix0) * CC);
        if (vx1 & vy1) v11 = *reinterpret_cast<const float4*>(vb + (size_t)(iy1 * Wd + ix1) * CC);

        const float w00 = wx0 * wy0, w10 = wx1 * wy0;
        const float w01 = wx0 * wy1, w11 = wx1 * wy1;
        acc.x = fmaf(awP, w00 * v00.x + w10 * v10.x + w01 * v01.x + w11 * v11.x, acc.x);
        acc.y = fmaf(awP, w00 * v00.y + w10 * v10.y + w01 * v01.y + w11 * v11.y, acc.y);
        acc.z = fmaf(awP, w00 * v00.z + w10 * v10.z + w01 * v01.z + w11 * v11.z, acc.z);
        acc.w = fmaf(awP, w00 * v00.w + w10 * v10.w + w01 * v01.w + w11 * v11.w, acc.w);
    }

#pragma unroll
    for (int o = 8; o <= 16; o <<= 1) {
        acc.x += __shfl_xor_sync(FULL, acc.x, o);
        acc.y += __shfl_xor_sync(FULL, acc.y, o);
        acc.z += __shfl_xor_sync(FULL, acc.z, o);
        acc.w += __shfl_xor_sync(FULL, acc.w, o);
    }

    if (g == 0)
        *reinterpret_cast<float4*>(out + (size_t)bq * CC + h * DH + c4) = acc;
}

// ---------------------------------------------------------------------------
// kernel_launch
// ---------------------------------------------------------------------------
extern "C" void kernel_launch(void* const* d_in, const int* in_sizes, int n_in,
                              void* d_out, int out_size)
{
    const float* query        = (const float*)d_in[0];
    const float* value_levels = (const float*)d_in[1];
    const float* refp         = (const float*)d_in[2];
    const float* W_off  = (const float*)d_in[4];
    const float* b_off  = (const float*)d_in[5];
    const float* W_attn = (const float*)d_in[6];
    const float* b_attn = (const float*)d_in[7];
    const float* W_val  = (const float*)d_in[8];
    const float* b_val  = (const float*)d_in[9];
    const float* W_out  = (const float*)d_in[10];
    const float* b_out  = (const float*)d_in[11];
    float* out = (float*)d_out;

    float *gv, *gq, *gt, *bc;
    cudaGetSymbolAddress((void**)&gv, g_value);
    cudaGetSymbolAddress((void**)&gq, g_qc);
    cudaGetSymbolAddress((void**)&gt, g_tout);
    cudaGetSymbolAddress((void**)&bc, g_bcat);
    __nv_bfloat16 *wpv, *wpq, *wpo;
    cudaGetSymbolAddress((void**)&wpv, g_wp_val);
    cudaGetSymbolAddress((void**)&wpq, g_wp_q);
    cudaGetSymbolAddress((void**)&wpo, g_wp_out);

    const int Mv = BB * STOT;   // 79788
    const int Mq = BB * NQ;     // 32000

    // 0) pre-split weights + concat bias
    conv_w3<<<256, 256>>>(W_val,  wpv, 256 * 256);
    conv_w3<<<256, 256>>>(W_off,  wpq, 256 * 256);
    conv_w3<<<128, 256>>>(W_attn, wpq + (size_t)256 * 768, 128 * 256);
    conv_w3<<<256, 256>>>(W_out,  wpo, 256 * 256);
    biascat<<<2, 256>>>(b_off, b_attn, bc);

    // 1) value projection (M=79788, N=256)
    gemm_ws<<<dim3((Mv + 127) / 128, 2), 256>>>(value_levels, wpv, b_val, gv, Mv, 256, 256);
    // 2) fused offsets + logits (M=32000, N=384)
    gemm_ws<<<dim3((Mq + 127) / 128, 3), 256>>>(query, wpq, bc, gq, Mq, 384, 256);
    // 3) fused softmax + bilinear sample + reduce
    msda_sampler<<<(BB * NQ * NHEAD) / 8, 256>>>(gv, gq, refp, gt);
    // 4) output projection (M=32000, N=256)
    gemm_ws<<<dim3((Mq + 127) / 128, 2), 256>>>(gt, wpo, b_out, out, Mq, 256, 256);
}

// round 17
// speedup vs baseline: 1.2031x; 1.2031x over previous
#include <cuda_runtime.h>
#include <cuda_bf16.h>
#include <cuda_fp16.h>
#include <math.h>
#include <stdint.h>

// Problem constants (fixed by the reference)
#define NHEAD 8
#define NLVL 4
#define NPNT 4
#define BB 4
#define NQ 8000
#define CC 256
#define DH 32
#define STOT 19947   // 100*150 + 50*75 + 25*38 + 13*19

// Scratch (static device globals: allocation-free)
static __device__ float g_value[(size_t)BB * STOT * CC];     // [B,S,C]
static __device__ float g_qc   [(size_t)BB * NQ * 384];      // fused [off(256) | logits(128)]
static __device__ float g_tout [(size_t)BB * NQ * CC];

// Pre-packed fp16 weights: per fp32 -> word (hi | hi<<16); [N][256] uint32
static __device__ uint32_t g_wp_val[(size_t)256 * 256];
static __device__ uint32_t g_wp_q  [(size_t)384 * 256];   // W_off rows 0..255, W_attn 256..383
static __device__ uint32_t g_wp_out[(size_t)256 * 256];
static __device__ float g_bcat[384];

// ---------------------------------------------------------------------------
// Weight pre-pack: W[i] -> round_fp16 duplicated into one uint32
// ---------------------------------------------------------------------------
__global__ void conv_w2(const float* __restrict__ W, uint32_t* __restrict__ out, int n)
{
    int i = blockIdx.x * 256 + threadIdx.x;
    if (i >= n) return;
    uint32_t hb = (uint32_t)__half_as_ushort(__float2half(W[i]));
    out[i] = hb | (hb << 16);
}

__global__ void biascat(const float* __restrict__ b0, const float* __restrict__ b1,
                        float* __restrict__ out)
{
    int i = blockIdx.x * 256 + threadIdx.x;
    if (i < 256) out[i] = b0[i];
    else if (i < 384) out[i] = b1[i - 256];
}

// ---------------------------------------------------------------------------
// 2-product split-fp16 tensor-core GEMM (HMMA mma.sync; tcgen05 rejected by
// the harness's compute_103 ptxas target).
// C[m,n] = sum_k A[m,k]*W[n,k] + bias[n]; fp32 in/out.
// A -> [hiA, loA] fp16 in-loop (exact: hiA+loA == A to 2^-23); W pre-rounded
// to fp16 [hiB, hiB]. GEMM computes A*hiB; only error is W's fp16 rounding.
// k-tile = 16 fp32 = 32 fp16 slots = 2 k16 MMA steps (was 3 with bf16 split).
// CTA tile 128x128, 8 warps (warp tile 64x32).
// ---------------------------------------------------------------------------
#define GS2 40           // padded smem row stride in fp16 (80B, conflict-free)

__device__ __forceinline__ void mma16816(float* d, const uint32_t* a, const uint32_t* b)
{
    asm volatile(
        "mma.sync.aligned.m16n8k16.row.col.f32.f16.f16.f32 "
        "{%0,%1,%2,%3}, {%4,%5,%6,%7}, {%8,%9}, {%0,%1,%2,%3};\n"
        : "+f"(d[0]), "+f"(d[1]), "+f"(d[2]), "+f"(d[3])
        : "r"(a[0]), "r"(a[1]), "r"(a[2]), "r"(a[3]), "r"(b[0]), "r"(b[1]));
}

// fp32x4 -> 8 fp16 slots [hi0,lo0,hi1,lo1,hi2,lo2,hi3,lo3] packed as uint4
__device__ __forceinline__ uint4 split_pack_A2(float4 v)
{
    const float f[4] = {v.x, v.y, v.z, v.w};
    uint32_t w[4];
#pragma unroll
    for (int j = 0; j < 4; j++) {
        __half h = __float2half(f[j]);
        __half l = __float2half(f[j] - __half2float(h));
        w[j] = (uint32_t)__half_as_ushort(h) | ((uint32_t)__half_as_ushort(l) << 16);
    }
    return make_uint4(w[0], w[1], w[2], w[3]);
}

__global__ __launch_bounds__(256, 2) void gemm_ws(
    const float* __restrict__ A, const uint32_t* __restrict__ Wp,
    const float* __restrict__ bias, float* __restrict__ C,
    int M, int N, int K)
{
    __shared__ __half As[128 * GS2];
    __shared__ __half Bs[128 * GS2];

    const int tid  = threadIdx.x;
    const int lane = tid & 31;
    const int warp = tid >> 5;
    const int warpM = warp & 1;       // 0..1  (64-row groups)
    const int warpN = warp >> 1;      // 0..3  (32-col groups)
    const int m0 = blockIdx.x * 128;
    const int n0 = blockIdx.y * 128;

    float acc[4][4][4];
#pragma unroll
    for (int i = 0; i < 4; i++)
#pragma unroll
        for (int j = 0; j < 4; j++)
#pragma unroll
            for (int r = 0; r < 4; r++) acc[i][j][r] = 0.f;

    // loaders: per k-tile, A: 512 float4 chunks; W: 512 uint4 chunks; 2 each/thread
    const int ar0 = tid >> 2,          ac0 = tid & 3;
    const int ar1 = (tid + 256) >> 2,  ac1 = (tid + 256) & 3;
    const uint4* WpV = reinterpret_cast<const uint4*>(Wp);   // row stride = 64 uint4

    float4 pa0, pa1;
    uint4  pw0, pw1;

    // prefetch tile 0
    {
        pa0 = make_float4(0.f, 0.f, 0.f, 0.f); pa1 = pa0;
        if (m0 + ar0 < M) pa0 = reinterpret_cast<const float4*>(A + (size_t)(m0 + ar0) * K)[ac0];
        if (m0 + ar1 < M) pa1 = reinterpret_cast<const float4*>(A + (size_t)(m0 + ar1) * K)[ac1];
        pw0 = WpV[(size_t)(n0 + ar0) * 64 + ac0];
        pw1 = WpV[(size_t)(n0 + ar1) * 64 + ac1];
    }

    const int nTiles = K / 16;
    for (int t = 0; t < nTiles; t++) {
        __syncthreads();
        {
            *reinterpret_cast<uint4*>(&As[ar0 * GS2 + ac0 * 8]) = split_pack_A2(pa0);
            *reinterpret_cast<uint4*>(&As[ar1 * GS2 + ac1 * 8]) = split_pack_A2(pa1);
            *reinterpret_cast<uint4*>(&Bs[ar0 * GS2 + ac0 * 8]) = pw0;
            *reinterpret_cast<uint4*>(&Bs[ar1 * GS2 + ac1 * 8]) = pw1;
        }
        __syncthreads();

        if (t + 1 < nTiles) {
            const int k0 = (t + 1) * 16;
            pa0 = make_float4(0.f, 0.f, 0.f, 0.f); pa1 = pa0;
            if (m0 + ar0 < M) pa0 = reinterpret_cast<const float4*>(A + (size_t)(m0 + ar0) * K + k0)[ac0];
            if (m0 + ar1 < M) pa1 = reinterpret_cast<const float4*>(A + (size_t)(m0 + ar1) * K + k0)[ac1];
            pw0 = WpV[(size_t)(n0 + ar0) * 64 + (t + 1) * 4 + ac0];
            pw1 = WpV[(size_t)(n0 + ar1) * 64 + (t + 1) * 4 + ac1];
        }

        // compute: 2 k16-steps over the 32 fp16 slots
#pragma unroll
        for (int ks = 0; ks < 2; ks++) {
            uint32_t bfr[4][2];
#pragma unroll
            for (int an = 0; an < 4; an++) {
                const uint32_t* bp = reinterpret_cast<const uint32_t*>(
                    &Bs[(warpN * 32 + an * 8 + (lane >> 2)) * GS2 + ks * 16 + (lane & 3) * 2]);
                bfr[an][0] = bp[0];
                bfr[an][1] = bp[4];      // +8 fp16
            }
#pragma unroll
            for (int am = 0; am < 4; am++) {
                const uint32_t* ap = reinterpret_cast<const uint32_t*>(
                    &As[(warpM * 64 + am * 16 + (lane >> 2)) * GS2 + ks * 16 + (lane & 3) * 2]);
                uint32_t afr[4];
                afr[0] = ap[0];
                afr[1] = ap[8 * GS2 / 2];        // +8 rows
                afr[2] = ap[4];                  // +8 fp16
                afr[3] = ap[8 * GS2 / 2 + 4];
#pragma unroll
                for (int an = 0; an < 4; an++)
                    mma16816(acc[am][an], afr, bfr[an]);
            }
        }
    }

    // epilogue: add bias, store fp32
#pragma unroll
    for (int an = 0; an < 4; an++) {
        const int col = n0 + warpN * 32 + an * 8 + (lane & 3) * 2;
        const float b0v = bias[col], b1v = bias[col + 1];
#pragma unroll
        for (int am = 0; am < 4; am++) {
            const int row = m0 + warpM * 64 + am * 16 + (lane >> 2);
            if (row < M) {
                float2* p = reinterpret_cast<float2*>(C + (size_t)row * N + col);
                *p = make_float2(acc[am][an][0] + b0v, acc[am][an][1] + b1v);
            }
            if (row + 8 < M) {
                float2* p = reinterpret_cast<float2*>(C + (size_t)(row + 8) * N + col);
                *p = make_float2(acc[am][an][2] + b0v, acc[am][an][3] + b1v);
            }
        }
    }
}

// ---------------------------------------------------------------------------
// Fused softmax + bilinear sampling + attention reduce (unchanged).
// Reads fused qc: [B*Nq, 384] = [off(256) | logits(128)].
// ---------------------------------------------------------------------------
__global__ __launch_bounds__(256) void msda_sampler(
    const float* __restrict__ value, const float* __restrict__ qc,
    const float* __restrict__ refp, float* __restrict__ out)
{
    constexpr int LH[NLVL] = {100, 50, 25, 13};
    constexpr int LW[NLVL] = {150, 75, 38, 19};
    constexpr int LS[NLVL] = {0, 15000, 18750, 19700};

    const int gw   = (blockIdx.x << 3) + (threadIdx.x >> 5);
    const int lane = threadIdx.x & 31;
    if (gw >= BB * NQ * NHEAD) return;

    const int h  = gw & 7;
    const int bq = gw >> 3;
    const int b  = bq / NQ;
    const unsigned FULL = 0xffffffffu;

    const float* qrow = qc + (size_t)bq * 384;

    const float* lg = qrow + 256 + h * 16;
    float myl = (lane < 16) ? lg[lane] : -1e30f;
    float mx = myl;
#pragma unroll
    for (int o = 16; o >= 1; o >>= 1) mx = fmaxf(mx, __shfl_xor_sync(FULL, mx, o));
    float e = (lane < 16) ? expf(myl - mx) : 0.f;
    float s = e;
#pragma unroll
    for (int o = 16; o >= 1; o >>= 1) s += __shfl_xor_sync(FULL, s, o);
    const float aw = e * (1.f / s);

    float px = 0.f, py = 0.f;
    if (lane < 16) {
        const int l = lane >> 2;
        const float2 o2 = *reinterpret_cast<const float2*>(qrow + h * 32 + lane * 2);
        const float2 r2 = *reinterpret_cast<const float2*>(refp + (size_t)bq * (NLVL * 2) + l * 2);
        const float fW = (l == 0) ? 150.f : (l == 1) ? 75.f : (l == 2) ? 38.f : 19.f;
        const float fH = (l == 0) ? 100.f : (l == 1) ? 50.f : (l == 2) ? 25.f : 13.f;
        px = (r2.x + o2.x / fW) * fW - 0.5f;
        py = (r2.y + o2.y / fH) * fH - 0.5f;
    }

    const int g  = lane >> 3;
    const int c4 = (lane & 7) << 2;
    float4 acc = make_float4(0.f, 0.f, 0.f, 0.f);

#pragma unroll
    for (int l = 0; l < NLVL; l++) {
        const int Hd = LH[l], Wd = LW[l];
        const int src = (l << 2) + g;
        const float xP  = __shfl_sync(FULL, px, src);
        const float yP  = __shfl_sync(FULL, py, src);
        const float awP = __shfl_sync(FULL, aw, src);

        const float xf = floorf(xP), yf = floorf(yP);
        const float wx1 = xP - xf, wy1 = yP - yf;
        const float wx0 = 1.f - wx1, wy0 = 1.f - wy1;
        const int ix0 = (int)xf, iy0 = (int)yf;
        const int ix1 = ix0 + 1, iy1 = iy0 + 1;

        const bool vx0 = (ix0 >= 0) & (ix0 < Wd);
        const bool vx1 = (ix1 >= 0) & (ix1 < Wd);
        const bool vy0 = (iy0 >= 0) & (iy0 < Hd);
        const bool vy1 = (iy1 >= 0) & (iy1 < Hd);

        const float* vb = value + ((size_t)(b * STOT + LS[l])) * CC + h * DH + c4;
        float4 v00 = make_float4(0.f, 0.f, 0.f, 0.f);
        float4 v10 = v00, v01 = v00, v11 = v00;
        if (vx0 & vy0) v00 = *reinterpret_cast<const float4*>(vb + (size_t)(iy0 * Wd + ix0) * CC);
        if (vx1 & vy0) v10 = *reinterpret_cast<const float4*>(vb + (size_t)(iy0 * Wd + ix1) * CC);
        if (vx0 & vy1) v01 = *reinterpret_cast<const float4*>(vb + (size_t)(iy1 * Wd + ix0) * CC);
        if (vx1 & vy1) v11 = *reinterpret_cast<const float4*>(vb + (size_t)(iy1 * Wd + ix1) * CC);

        const float w00 = wx0 * wy0, w10 = wx1 * wy0;
        const float w01 = wx0 * wy1, w11 = wx1 * wy1;
        acc.x = fmaf(awP, w00 * v00.x + w10 * v10.x + w01 * v01.x + w11 * v11.x, acc.x);
        acc.y = fmaf(awP, w00 * v00.y + w10 * v10.y + w01 * v01.y + w11 * v11.y, acc.y);
        acc.z = fmaf(awP, w00 * v00.z + w10 * v10.z + w01 * v01.z + w11 * v11.z, acc.z);
        acc.w = fmaf(awP, w00 * v00.w + w10 * v10.w + w01 * v01.w + w11 * v11.w, acc.w);
    }

#pragma unroll
    for (int o = 8; o <= 16; o <<= 1) {
        acc.x += __shfl_xor_sync(FULL, acc.x, o);
        acc.y += __shfl_xor_sync(FULL, acc.y, o);
        acc.z += __shfl_xor_sync(FULL, acc.z, o);
        acc.w += __shfl_xor_sync(FULL, acc.w, o);
    }

    if (g == 0)
        *reinterpret_cast<float4*>(out + (size_t)bq * CC + h * DH + c4) = acc;
}

// ---------------------------------------------------------------------------
// kernel_launch
// ---------------------------------------------------------------------------
extern "C" void kernel_launch(void* const* d_in, const int* in_sizes, int n_in,
                              void* d_out, int out_size)
{
    const float* query        = (const float*)d_in[0];
    const float* value_levels = (const float*)d_in[1];
    const float* refp         = (const float*)d_in[2];
    const float* W_off  = (const float*)d_in[4];
    const float* b_off  = (const float*)d_in[5];
    const float* W_attn = (const float*)d_in[6];
    const float* b_attn = (const float*)d_in[7];
    const float* W_val  = (const float*)d_in[8];
    const float* b_val  = (const float*)d_in[9];
    const float* W_out  = (const float*)d_in[10];
    const float* b_out  = (const float*)d_in[11];
    float* out = (float*)d_out;

    float *gv, *gq, *gt, *bc;
    cudaGetSymbolAddress((void**)&gv, g_value);
    cudaGetSymbolAddress((void**)&gq, g_qc);
    cudaGetSymbolAddress((void**)&gt, g_tout);
    cudaGetSymbolAddress((void**)&bc, g_bcat);
    uint32_t *wpv, *wpq, *wpo;
    cudaGetSymbolAddress((void**)&wpv, g_wp_val);
    cudaGetSymbolAddress((void**)&wpq, g_wp_q);
    cudaGetSymbolAddress((void**)&wpo, g_wp_out);

    const int Mv = BB * STOT;   // 79788
    const int Mq = BB * NQ;     // 32000

    // 0) pre-pack weights + concat bias
    conv_w2<<<256, 256>>>(W_val,  wpv, 256 * 256);
    conv_w2<<<256, 256>>>(W_off,  wpq, 256 * 256);
    conv_w2<<<128, 256>>>(W_attn, wpq + (size_t)256 * 256, 128 * 256);
    conv_w2<<<256, 256>>>(W_out,  wpo, 256 * 256);
    biascat<<<2, 256>>>(b_off, b_attn, bc);

    // 1) value projection (M=79788, N=256)
    gemm_ws<<<dim3((Mv + 127) / 128, 2), 256>>>(value_levels, wpv, b_val, gv, Mv, 256, 256);
    // 2) fused offsets + logits (M=32000, N=384)
    gemm_ws<<<dim3((Mq + 127) / 128, 3), 256>>>(query, wpq, bc, gq, Mq, 384, 256);
    // 3) fused softmax + bilinear sample + reduce
    msda_sampler<<<(BB * NQ * NHEAD) / 8, 256>>>(gv, gq, refp, gt);
    // 4) output projection (M=32000, N=256)
    gemm_ws<<<dim3((Mq + 127) / 128, 2), 256>>>(gt, wpo, b_out, out, Mq, 256, 256);
}